// round 1
// baseline (speedup 1.0000x reference)
#include <cuda_runtime.h>
#include <cuda_bf16.h>
#include <cstdint>

// Problem constants
#define NE     8
#define HID    2048
#define INTER  5632
#define TOK    2048
#define TOPK   2
#define NP     (TOK * TOPK)   // 4096 (token, k) pairs

// Tiling
#define BM 64
#define BN 64
#define BK 16
#define NTHREADS 256

// Static scratch (no allocations allowed)
__device__ int   d_offsets[NE + 1];
__device__ int   d_pairs[NP];                       // pair ids grouped by expert
__device__ float d_h[(size_t)NP * INTER];           // silu(x*w1) * (x*w3)
__device__ float d_y[(size_t)NP * HID];             // per-pair weighted output

// ---------------------------------------------------------------------------
// Group the 4096 (token,k) pairs by expert. Single block.
// ---------------------------------------------------------------------------
__global__ void build_groups(const int* __restrict__ expert_indices) {
    __shared__ int s_cnt[NE];
    __shared__ int s_off[NE + 1];
    int tid = threadIdx.x;
    if (tid < NE) s_cnt[tid] = 0;
    __syncthreads();
    for (int p = tid; p < NP; p += blockDim.x)
        atomicAdd(&s_cnt[expert_indices[p]], 1);
    __syncthreads();
    if (tid == 0) {
        s_off[0] = 0;
        for (int e = 0; e < NE; e++) s_off[e + 1] = s_off[e] + s_cnt[e];
    }
    __syncthreads();
    if (tid <= NE) d_offsets[tid] = s_off[tid];
    if (tid < NE) s_cnt[tid] = s_off[tid];   // reuse as scatter cursor
    __syncthreads();
    for (int p = tid; p < NP; p += blockDim.x) {
        int e = expert_indices[p];
        int pos = atomicAdd(&s_cnt[e], 1);
        d_pairs[pos] = p;
    }
}

// ---------------------------------------------------------------------------
// GEMM1: h[pair, n] = silu(x[tok]*w1[e])[n] * (x[tok]*w3[e])[n]
// A: gathered x rows [cnt x HID], B: w1/w3 [HID x INTER] (row-major, n contig)
// grid: (INTER/BN, NE, maxTiles)
// ---------------------------------------------------------------------------
__global__ void gemm1_kernel(const float* __restrict__ x,
                             const float* __restrict__ w1,
                             const float* __restrict__ w3) {
    const int e    = blockIdx.y;
    const int base = d_offsets[e];
    const int cnt  = d_offsets[e + 1] - base;
    const int m0   = blockIdx.z * BM;
    if (m0 >= cnt) return;
    const int n0 = blockIdx.x * BN;

    __shared__ float As[BK][BM];
    __shared__ float Bs1[BK][BN];
    __shared__ float Bs3[BK][BN];
    __shared__ int   s_pid[BM];
    __shared__ int   s_tok[BM];

    const int tid = threadIdx.x;
    if (tid < BM) {
        int gm = m0 + tid;
        if (gm < cnt) {
            int p = d_pairs[base + gm];
            s_pid[tid] = p;
            s_tok[tid] = p >> 1;   // TOPK == 2
        } else {
            s_pid[tid] = -1;
            s_tok[tid] = 0;
        }
    }
    __syncthreads();

    const float* w1e = w1 + (size_t)e * HID * INTER;
    const float* w3e = w3 + (size_t)e * HID * INTER;

    const int tx = tid & 15;   // n direction
    const int ty = tid >> 4;   // m direction

    float accg[4][4];
    float accu[4][4];
#pragma unroll
    for (int i = 0; i < 4; i++)
#pragma unroll
        for (int j = 0; j < 4; j++) { accg[i][j] = 0.f; accu[i][j] = 0.f; }

    const int a_r  = tid >> 2;          // 0..63
    const int a_k  = (tid & 3) * 4;     // 0,4,8,12
    const int b_k  = tid >> 4;          // 0..15
    const int b_n  = (tid & 15) * 4;    // 0..60

    for (int k0 = 0; k0 < HID; k0 += BK) {
        // load A (gathered x) transposed into As[k][m]
        float4 va = make_float4(0.f, 0.f, 0.f, 0.f);
        if (s_pid[a_r] >= 0)
            va = *(const float4*)(x + (size_t)s_tok[a_r] * HID + k0 + a_k);
        As[a_k + 0][a_r] = va.x;
        As[a_k + 1][a_r] = va.y;
        As[a_k + 2][a_r] = va.z;
        As[a_k + 3][a_r] = va.w;
        // load B tiles
        size_t boff = (size_t)(k0 + b_k) * INTER + n0 + b_n;
        *(float4*)&Bs1[b_k][b_n] = *(const float4*)(w1e + boff);
        *(float4*)&Bs3[b_k][b_n] = *(const float4*)(w3e + boff);
        __syncthreads();

#pragma unroll
        for (int kk = 0; kk < BK; kk++) {
            float a[4], b1[4], b3[4];
            *(float4*)a  = *(float4*)&As[kk][ty * 4];
            *(float4*)b1 = *(float4*)&Bs1[kk][tx * 4];
            *(float4*)b3 = *(float4*)&Bs3[kk][tx * 4];
#pragma unroll
            for (int i = 0; i < 4; i++)
#pragma unroll
                for (int j = 0; j < 4; j++) {
                    accg[i][j] += a[i] * b1[j];
                    accu[i][j] += a[i] * b3[j];
                }
        }
        __syncthreads();
    }

#pragma unroll
    for (int i = 0; i < 4; i++) {
        int m = ty * 4 + i;
        int p = s_pid[m];
        if (p < 0) continue;
        float* hrow = d_h + (size_t)p * INTER + n0 + tx * 4;
#pragma unroll
        for (int j = 0; j < 4; j++) {
            float g = accg[i][j];
            float u = accu[i][j];
            float s = g / (1.f + __expf(-g));
            hrow[j] = s * u;
        }
    }
}

// ---------------------------------------------------------------------------
// GEMM2: y[pair, n] = ew[pair] * (h[pair,:] . w2[e][:,n])
// A: d_h [cnt x INTER], B: w2 [INTER x HID] (n contig)
// grid: (HID/BN, NE, maxTiles)
// ---------------------------------------------------------------------------
__global__ void gemm2_kernel(const float* __restrict__ w2,
                             const float* __restrict__ ew) {
    const int e    = blockIdx.y;
    const int base = d_offsets[e];
    const int cnt  = d_offsets[e + 1] - base;
    const int m0   = blockIdx.z * BM;
    if (m0 >= cnt) return;
    const int n0 = blockIdx.x * BN;

    __shared__ float As[BK][BM];
    __shared__ float Bs[BK][BN];
    __shared__ int   s_pid[BM];

    const int tid = threadIdx.x;
    if (tid < BM) {
        int gm = m0 + tid;
        s_pid[tid] = (gm < cnt) ? d_pairs[base + gm] : -1;
    }
    __syncthreads();

    const float* w2e = w2 + (size_t)e * INTER * HID;

    const int tx = tid & 15;
    const int ty = tid >> 4;

    float acc[4][4];
#pragma unroll
    for (int i = 0; i < 4; i++)
#pragma unroll
        for (int j = 0; j < 4; j++) acc[i][j] = 0.f;

    const int a_r = tid >> 2;
    const int a_k = (tid & 3) * 4;
    const int b_k = tid >> 4;
    const int b_n = (tid & 15) * 4;

    for (int k0 = 0; k0 < INTER; k0 += BK) {
        float4 va = make_float4(0.f, 0.f, 0.f, 0.f);
        if (s_pid[a_r] >= 0)
            va = *(const float4*)(d_h + (size_t)s_pid[a_r] * INTER + k0 + a_k);
        As[a_k + 0][a_r] = va.x;
        As[a_k + 1][a_r] = va.y;
        As[a_k + 2][a_r] = va.z;
        As[a_k + 3][a_r] = va.w;
        size_t boff = (size_t)(k0 + b_k) * HID + n0 + b_n;
        *(float4*)&Bs[b_k][b_n] = *(const float4*)(w2e + boff);
        __syncthreads();

#pragma unroll
        for (int kk = 0; kk < BK; kk++) {
            float a[4], b[4];
            *(float4*)a = *(float4*)&As[kk][ty * 4];
            *(float4*)b = *(float4*)&Bs[kk][tx * 4];
#pragma unroll
            for (int i = 0; i < 4; i++)
#pragma unroll
                for (int j = 0; j < 4; j++)
                    acc[i][j] += a[i] * b[j];
        }
        __syncthreads();
    }

#pragma unroll
    for (int i = 0; i < 4; i++) {
        int m = ty * 4 + i;
        int p = s_pid[m];
        if (p < 0) continue;
        float w = ew[p];
        float* yrow = d_y + (size_t)p * HID + n0 + tx * 4;
#pragma unroll
        for (int j = 0; j < 4; j++)
            yrow[j] = acc[i][j] * w;
    }
}

// ---------------------------------------------------------------------------
// Combine: out[t, h] = y[2t, h] + y[2t+1, h]
// ---------------------------------------------------------------------------
__global__ void combine_kernel(float* __restrict__ out) {
    int idx = blockIdx.x * blockDim.x + threadIdx.x;
    if (idx >= TOK * HID) return;
    int t = idx / HID;
    int h = idx - t * HID;
    out[idx] = d_y[(size_t)(2 * t) * HID + h] + d_y[(size_t)(2 * t + 1) * HID + h];
}

// ---------------------------------------------------------------------------
extern "C" void kernel_launch(void* const* d_in, const int* in_sizes, int n_in,
                              void* d_out, int out_size) {
    const float* x   = (const float*)d_in[0];
    const float* ew  = (const float*)d_in[1];
    const float* w1  = (const float*)d_in[2];
    const float* w2  = (const float*)d_in[3];
    const float* w3  = (const float*)d_in[4];
    const int*   idx = (const int*)d_in[5];
    float* out = (float*)d_out;

    build_groups<<<1, 256>>>(idx);

    const int maxTiles = (NP + BM - 1) / BM;  // 64: worst case all pairs on one expert
    dim3 g1(INTER / BN, NE, maxTiles);
    gemm1_kernel<<<g1, NTHREADS>>>(x, w1, w3);

    dim3 g2(HID / BN, NE, maxTiles);
    gemm2_kernel<<<g2, NTHREADS>>>(w2, ew);

    combine_kernel<<<(TOK * HID + 255) / 256, 256>>>(out);
}

// round 6
// speedup vs baseline: 2.6295x; 2.6295x over previous
#include <cuda_runtime.h>
#include <cuda_bf16.h>
#include <cstdint>

#define NE     8
#define HID    2048
#define INTER  5632
#define TOK    2048
#define TOPK   2
#define NP     (TOK * TOPK)   // 4096

#define BM 128
#define BN 64
#define BK 64
#define NTHREADS 256
#define MTILES (NP / BM)      // 32

// Static scratch
__device__ int   d_offsets[NE + 1];
__device__ int   d_pairs[NP];
__device__ int   d_slot[NP];
__device__ float d_h[(size_t)NP * INTER];   // silu(x*w1) * (x*w3), sorted rows
__device__ float d_y[(size_t)NP * HID];     // weighted per-pair out, sorted rows

// ---------------------------------------------------------------------------
__global__ void build_groups(const int* __restrict__ expert_indices) {
    __shared__ int s_cnt[NE];
    __shared__ int s_off[NE + 1];
    int tid = threadIdx.x;
    if (tid < NE) s_cnt[tid] = 0;
    __syncthreads();
    for (int p = tid; p < NP; p += blockDim.x)
        atomicAdd(&s_cnt[expert_indices[p]], 1);
    __syncthreads();
    if (tid == 0) {
        s_off[0] = 0;
        for (int e = 0; e < NE; e++) s_off[e + 1] = s_off[e] + s_cnt[e];
    }
    __syncthreads();
    if (tid <= NE) d_offsets[tid] = s_off[tid];
    if (tid < NE) s_cnt[tid] = s_off[tid];
    __syncthreads();
    for (int p = tid; p < NP; p += blockDim.x) {
        int e = expert_indices[p];
        int pos = atomicAdd(&s_cnt[e], 1);
        d_pairs[pos] = p;
        d_slot[p] = pos;
    }
}

// ---------------------------------------------------------------------------
// helpers (identical machinery to prior round)
// ---------------------------------------------------------------------------
__device__ __forceinline__ uint32_t pack_bf16rn(float lo_elem, float hi_elem) {
    uint32_t r;
    asm("cvt.rn.bf16x2.f32 %0, %1, %2;" : "=r"(r) : "f"(hi_elem), "f"(lo_elem));
    return r;
}

// split 8 floats into 8 hi-bf16 (truncated) and 8 lo-bf16 (rounded residual)
__device__ __forceinline__ void cvt_split8(float4 v0, float4 v1, uint4& hi, uint4& lo) {
    float f[8] = {v0.x, v0.y, v0.z, v0.w, v1.x, v1.y, v1.z, v1.w};
    uint32_t h[4], l[4];
#pragma unroll
    for (int j = 0; j < 4; j++) {
        float a = f[2 * j], b = f[2 * j + 1];
        uint32_t ab = __float_as_uint(a) & 0xffff0000u;
        uint32_t bb = __float_as_uint(b) & 0xffff0000u;
        h[j] = (ab >> 16) | bb;             // low16 = a_hi, high16 = b_hi
        float ra = a - __uint_as_float(ab);
        float rb = b - __uint_as_float(bb);
        l[j] = pack_bf16rn(ra, rb);
    }
    hi = make_uint4(h[0], h[1], h[2], h[3]);
    lo = make_uint4(l[0], l[1], l[2], l[3]);
}

#define LDMX4(r0, r1, r2, r3, addr) \
    asm volatile("ldmatrix.sync.aligned.m8n8.x4.shared.b16 {%0,%1,%2,%3}, [%4];" \
                 : "=r"(r0), "=r"(r1), "=r"(r2), "=r"(r3) : "r"(addr))

#define LDMX4T(r0, r1, r2, r3, addr) \
    asm volatile("ldmatrix.sync.aligned.m8n8.x4.trans.shared.b16 {%0,%1,%2,%3}, [%4];" \
                 : "=r"(r0), "=r"(r1), "=r"(r2), "=r"(r3) : "r"(addr))

#define MMA16816(c, a, b0v, b1v) \
    asm volatile("mma.sync.aligned.m16n8k16.row.col.f32.bf16.bf16.f32 " \
                 "{%0,%1,%2,%3}, {%4,%5,%6,%7}, {%8,%9}, {%0,%1,%2,%3};" \
                 : "+f"(c[0]), "+f"(c[1]), "+f"(c[2]), "+f"(c[3]) \
                 : "r"(a[0]), "r"(a[1]), "r"(a[2]), "r"(a[3]), "r"(b0v), "r"(b1v))

// A-tile smem: 128 rows x 64 bf16 cols = 128B/row, xor-swizzled 16B chunks
// B-tile smem: 64 rows x 64 bf16 cols  = 128B/row, same swizzle
// ---------------------------------------------------------------------------
// Fused GEMM1: h = silu(x*w1) * (x*w3)   [A = gathered x, K=HID, N=INTER]
// grid: (MTILES, NE, INTER/BN)
// ---------------------------------------------------------------------------
__global__ __launch_bounds__(NTHREADS, 2)
void moe_gemm_fused(const float* __restrict__ x,
                    const float* __restrict__ w1,
                    const float* __restrict__ w3) {
    const int e    = blockIdx.y;
    const int base = d_offsets[e];
    const int cnt  = d_offsets[e + 1] - base;
    const int m0   = blockIdx.x * BM;
    if (m0 >= cnt) return;
    const int n0 = blockIdx.z * BN;

    extern __shared__ char smem[];
    char* pA_hi = smem;             // 16KB
    char* pA_lo = smem + 16384;     // 16KB
    char* pB1_hi = smem + 32768;    // 8KB
    char* pB1_lo = smem + 40960;
    char* pB3_hi = smem + 49152;
    char* pB3_lo = smem + 57344;
    const uint32_t sbase = (uint32_t)__cvta_generic_to_shared(smem);
    const uint32_t sA_hi = sbase, sA_lo = sbase + 16384;
    const uint32_t sB1_hi = sbase + 32768, sB1_lo = sbase + 40960;
    const uint32_t sB3_hi = sbase + 49152, sB3_lo = sbase + 57344;

    __shared__ int s_tok[BM];   // token id, or -1 past cnt

    const int tid = threadIdx.x;
    if (tid < BM) {
        int gm = m0 + tid;
        s_tok[tid] = (gm < cnt) ? (d_pairs[base + gm] >> 1) : -1;
    }
    __syncthreads();

    const float* w1e = w1 + (size_t)e * HID * INTER;
    const float* w3e = w3 + (size_t)e * HID * INTER;

    const int lane = tid & 31;
    const int warp = tid >> 5;
    const int wm = warp & 3;       // 4 m-slices of 32 rows
    const int wn = warp >> 2;      // 2 n-slices of 32 cols
    const int g  = lane >> 3;
    const int gr = lane & 7;

    int arow[2], arow7[2];
#pragma unroll
    for (int mi = 0; mi < 2; mi++) {
        arow[mi]  = wm * 32 + mi * 16 + ((g & 1) << 3) + gr;
        arow7[mi] = arow[mi] & 7;
    }
    const int brow_base = ((g & 1) << 3) + gr;
    const int g2 = g >> 1;

    float accg[2][4][4];
    float accu[2][4][4];
#pragma unroll
    for (int i = 0; i < 2; i++)
#pragma unroll
        for (int j = 0; j < 4; j++)
#pragma unroll
            for (int q = 0; q < 4; q++) { accg[i][j][q] = 0.f; accu[i][j][q] = 0.f; }

    for (int kt = 0; kt < HID; kt += BK) {
        __syncthreads();
        // A tile: 128 rows x 64 cols fp32 -> hi/lo bf16 (4 x 256 slots of 8 floats)
#pragma unroll
        for (int it = 0; it < 4; it++) {
            int i = tid + it * 256;
            int r = i >> 3, c = i & 7;
            float4 v0 = make_float4(0, 0, 0, 0), v1 = v0;
            int tok = s_tok[r];
            if (tok >= 0) {
                const float* src = x + (size_t)tok * HID + kt + c * 8;
                v0 = *(const float4*)src;
                v1 = *(const float4*)(src + 4);
            }
            uint4 hi, lo;
            cvt_split8(v0, v1, hi, lo);
            uint32_t off = (uint32_t)(r * 128 + ((c ^ (r & 7)) << 4));
            *(uint4*)(pA_hi + off) = hi;
            *(uint4*)(pA_lo + off) = lo;
        }
        // B tiles (w1 and w3): 64 rows x 64 cols each (2 x 256 slots per matrix)
#pragma unroll
        for (int it = 0; it < 2; it++) {
            int i = tid + it * 256;
            int k = i >> 3, c = i & 7;
            size_t boff = (size_t)(kt + k) * INTER + n0 + c * 8;
            uint32_t off = (uint32_t)(k * 128 + ((c ^ (k & 7)) << 4));
            {
                float4 v0 = *(const float4*)(w1e + boff);
                float4 v1 = *(const float4*)(w1e + boff + 4);
                uint4 hi, lo;
                cvt_split8(v0, v1, hi, lo);
                *(uint4*)(pB1_hi + off) = hi;
                *(uint4*)(pB1_lo + off) = lo;
            }
            {
                float4 v0 = *(const float4*)(w3e + boff);
                float4 v1 = *(const float4*)(w3e + boff + 4);
                uint4 hi, lo;
                cvt_split8(v0, v1, hi, lo);
                *(uint4*)(pB3_hi + off) = hi;
                *(uint4*)(pB3_lo + off) = lo;
            }
        }
        __syncthreads();

#pragma unroll
        for (int ks = 0; ks < 4; ks++) {
            uint32_t afh[2][4], afl[2][4];
#pragma unroll
            for (int mi = 0; mi < 2; mi++) {
                int c = ks * 2 + g2;
                uint32_t off = (uint32_t)(arow[mi] * 128 + ((c ^ arow7[mi]) << 4));
                LDMX4(afh[mi][0], afh[mi][1], afh[mi][2], afh[mi][3], sA_hi + off);
                LDMX4(afl[mi][0], afl[mi][1], afl[mi][2], afl[mi][3], sA_lo + off);
            }
            int kb = ks * 16 + brow_base;
#pragma unroll
            for (int nj = 0; nj < 2; nj++) {
                int cb = wn * 4 + nj * 2 + g2;
                uint32_t off = (uint32_t)(kb * 128 + ((cb ^ (kb & 7)) << 4));
                // ---- w1 -> accg
                {
                    uint32_t bh[4], bl[4];
                    LDMX4T(bh[0], bh[1], bh[2], bh[3], sB1_hi + off);
                    LDMX4T(bl[0], bl[1], bl[2], bl[3], sB1_lo + off);
#pragma unroll
                    for (int mi = 0; mi < 2; mi++)
#pragma unroll
                        for (int ns = 0; ns < 2; ns++) {
                            float* c = accg[mi][nj * 2 + ns];
                            MMA16816(c, afh[mi], bh[ns * 2], bh[ns * 2 + 1]);
                            MMA16816(c, afh[mi], bl[ns * 2], bl[ns * 2 + 1]);
                            MMA16816(c, afl[mi], bh[ns * 2], bh[ns * 2 + 1]);
                        }
                }
                // ---- w3 -> accu
                {
                    uint32_t bh[4], bl[4];
                    LDMX4T(bh[0], bh[1], bh[2], bh[3], sB3_hi + off);
                    LDMX4T(bl[0], bl[1], bl[2], bl[3], sB3_lo + off);
#pragma unroll
                    for (int mi = 0; mi < 2; mi++)
#pragma unroll
                        for (int ns = 0; ns < 2; ns++) {
                            float* c = accu[mi][nj * 2 + ns];
                            MMA16816(c, afh[mi], bh[ns * 2], bh[ns * 2 + 1]);
                            MMA16816(c, afh[mi], bl[ns * 2], bl[ns * 2 + 1]);
                            MMA16816(c, afl[mi], bh[ns * 2], bh[ns * 2 + 1]);
                        }
                }
            }
        }
    }

    // epilogue: h = silu(g) * u, sorted-row storage
    const int mrow = lane >> 2;
    const int ncol = (lane & 3) * 2;
#pragma unroll
    for (int mi = 0; mi < 2; mi++) {
        int mrel0 = wm * 32 + mi * 16 + mrow;
        int mrel1 = mrel0 + 8;
        bool v0r = (m0 + mrel0) < cnt;
        bool v1r = (m0 + mrel1) < cnt;
        size_t srow0 = (size_t)(base + m0 + mrel0);
        size_t srow1 = (size_t)(base + m0 + mrel1);
#pragma unroll
        for (int n8 = 0; n8 < 4; n8++) {
            int col = n0 + wn * 32 + n8 * 8 + ncol;
            float* gA = accg[mi][n8];
            float* uA = accu[mi][n8];
            if (v0r) {
                float h0 = (gA[0] / (1.f + __expf(-gA[0]))) * uA[0];
                float h1 = (gA[1] / (1.f + __expf(-gA[1]))) * uA[1];
                *(float2*)(d_h + srow0 * INTER + col) = make_float2(h0, h1);
            }
            if (v1r) {
                float h0 = (gA[2] / (1.f + __expf(-gA[2]))) * uA[2];
                float h1 = (gA[3] / (1.f + __expf(-gA[3]))) * uA[3];
                *(float2*)(d_h + srow1 * INTER + col) = make_float2(h0, h1);
            }
        }
    }
}

// ---------------------------------------------------------------------------
// GEMM2: y = ew * (h * w2)   [A = d_h sorted rows, K=INTER, N=HID]
// grid: (MTILES, NE, HID/BN)
// ---------------------------------------------------------------------------
__global__ __launch_bounds__(NTHREADS, 2)
void moe_gemm2(const float* __restrict__ w2,
               const float* __restrict__ ew) {
    const int e    = blockIdx.y;
    const int base = d_offsets[e];
    const int cnt  = d_offsets[e + 1] - base;
    const int m0   = blockIdx.x * BM;
    if (m0 >= cnt) return;
    const int n0 = blockIdx.z * BN;

    extern __shared__ char smem[];
    char* pA_hi = smem;
    char* pA_lo = smem + 16384;
    char* pB_hi = smem + 32768;
    char* pB_lo = smem + 40960;
    const uint32_t sbase = (uint32_t)__cvta_generic_to_shared(smem);
    const uint32_t sA_hi = sbase, sA_lo = sbase + 16384;
    const uint32_t sB_hi = sbase + 32768, sB_lo = sbase + 40960;

    __shared__ int   s_valid[BM];
    __shared__ float s_w[BM];

    const int tid = threadIdx.x;
    if (tid < BM) {
        int gm = m0 + tid;
        if (gm < cnt) {
            s_valid[tid] = 1;
            s_w[tid] = ew[d_pairs[base + gm]];
        } else {
            s_valid[tid] = 0;
            s_w[tid] = 0.f;
        }
    }
    __syncthreads();

    const float* w2e = w2 + (size_t)e * INTER * HID;

    const int lane = tid & 31;
    const int warp = tid >> 5;
    const int wm = warp & 3;
    const int wn = warp >> 2;
    const int g  = lane >> 3;
    const int gr = lane & 7;

    int arow[2], arow7[2];
#pragma unroll
    for (int mi = 0; mi < 2; mi++) {
        arow[mi]  = wm * 32 + mi * 16 + ((g & 1) << 3) + gr;
        arow7[mi] = arow[mi] & 7;
    }
    const int brow_base = ((g & 1) << 3) + gr;
    const int g2 = g >> 1;

    float acc[2][4][4];
#pragma unroll
    for (int i = 0; i < 2; i++)
#pragma unroll
        for (int j = 0; j < 4; j++)
#pragma unroll
            for (int q = 0; q < 4; q++) acc[i][j][q] = 0.f;

    for (int kt = 0; kt < INTER; kt += BK) {
        __syncthreads();
#pragma unroll
        for (int it = 0; it < 4; it++) {
            int i = tid + it * 256;
            int r = i >> 3, c = i & 7;
            float4 v0 = make_float4(0, 0, 0, 0), v1 = v0;
            if (s_valid[r]) {
                const float* src = d_h + (size_t)(base + m0 + r) * INTER + kt + c * 8;
                v0 = *(const float4*)src;
                v1 = *(const float4*)(src + 4);
            }
            uint4 hi, lo;
            cvt_split8(v0, v1, hi, lo);
            uint32_t off = (uint32_t)(r * 128 + ((c ^ (r & 7)) << 4));
            *(uint4*)(pA_hi + off) = hi;
            *(uint4*)(pA_lo + off) = lo;
        }
#pragma unroll
        for (int it = 0; it < 2; it++) {
            int i = tid + it * 256;
            int k = i >> 3, c = i & 7;
            const float* src = w2e + (size_t)(kt + k) * HID + n0 + c * 8;
            float4 v0 = *(const float4*)src;
            float4 v1 = *(const float4*)(src + 4);
            uint4 hi, lo;
            cvt_split8(v0, v1, hi, lo);
            uint32_t off = (uint32_t)(k * 128 + ((c ^ (k & 7)) << 4));
            *(uint4*)(pB_hi + off) = hi;
            *(uint4*)(pB_lo + off) = lo;
        }
        __syncthreads();

#pragma unroll
        for (int ks = 0; ks < 4; ks++) {
            uint32_t afh[2][4], afl[2][4];
#pragma unroll
            for (int mi = 0; mi < 2; mi++) {
                int c = ks * 2 + g2;
                uint32_t off = (uint32_t)(arow[mi] * 128 + ((c ^ arow7[mi]) << 4));
                LDMX4(afh[mi][0], afh[mi][1], afh[mi][2], afh[mi][3], sA_hi + off);
                LDMX4(afl[mi][0], afl[mi][1], afl[mi][2], afl[mi][3], sA_lo + off);
            }
            int kb = ks * 16 + brow_base;
#pragma unroll
            for (int nj = 0; nj < 2; nj++) {
                int cb = wn * 4 + nj * 2 + g2;
                uint32_t off = (uint32_t)(kb * 128 + ((cb ^ (kb & 7)) << 4));
                uint32_t bh[4], bl[4];
                LDMX4T(bh[0], bh[1], bh[2], bh[3], sB_hi + off);
                LDMX4T(bl[0], bl[1], bl[2], bl[3], sB_lo + off);
#pragma unroll
                for (int mi = 0; mi < 2; mi++)
#pragma unroll
                    for (int ns = 0; ns < 2; ns++) {
                        float* c = acc[mi][nj * 2 + ns];
                        MMA16816(c, afh[mi], bh[ns * 2], bh[ns * 2 + 1]);
                        MMA16816(c, afh[mi], bl[ns * 2], bl[ns * 2 + 1]);
                        MMA16816(c, afl[mi], bh[ns * 2], bh[ns * 2 + 1]);
                    }
            }
        }
    }

    const int mrow = lane >> 2;
    const int ncol = (lane & 3) * 2;
#pragma unroll
    for (int mi = 0; mi < 2; mi++) {
        int mrel0 = wm * 32 + mi * 16 + mrow;
        int mrel1 = mrel0 + 8;
        bool v0r = (m0 + mrel0) < cnt;
        bool v1r = (m0 + mrel1) < cnt;
        size_t srow0 = (size_t)(base + m0 + mrel0);
        size_t srow1 = (size_t)(base + m0 + mrel1);
#pragma unroll
        for (int n8 = 0; n8 < 4; n8++) {
            int col = n0 + wn * 32 + n8 * 8 + ncol;
            float* a = acc[mi][n8];
            if (v0r) {
                float w = s_w[mrel0];
                *(float2*)(d_y + srow0 * HID + col) = make_float2(a[0] * w, a[1] * w);
            }
            if (v1r) {
                float w = s_w[mrel1];
                *(float2*)(d_y + srow1 * HID + col) = make_float2(a[2] * w, a[3] * w);
            }
        }
    }
}

// ---------------------------------------------------------------------------
__global__ void combine_kernel(float* __restrict__ out) {
    int idx = blockIdx.x * blockDim.x + threadIdx.x;   // float4 index
    if (idx >= TOK * HID / 4) return;
    int t = idx / (HID / 4);
    int h4 = idx - t * (HID / 4);
    size_t s0 = (size_t)d_slot[2 * t];
    size_t s1 = (size_t)d_slot[2 * t + 1];
    float4 y0 = *(const float4*)(d_y + s0 * HID + h4 * 4);
    float4 y1 = *(const float4*)(d_y + s1 * HID + h4 * 4);
    ((float4*)out)[idx] = make_float4(y0.x + y1.x, y0.y + y1.y, y0.z + y1.z, y0.w + y1.w);
}

// ---------------------------------------------------------------------------
extern "C" void kernel_launch(void* const* d_in, const int* in_sizes, int n_in,
                              void* d_out, int out_size) {
    const float* x   = (const float*)d_in[0];
    const float* ew  = (const float*)d_in[1];
    const float* w1  = (const float*)d_in[2];
    const float* w2  = (const float*)d_in[3];
    const float* w3  = (const float*)d_in[4];
    const int*   idx = (const int*)d_in[5];
    float* out = (float*)d_out;

    const int SMEM1 = 65536;
    const int SMEM2 = 49152;
    cudaFuncSetAttribute(moe_gemm_fused, cudaFuncAttributeMaxDynamicSharedMemorySize, SMEM1);
    cudaFuncSetAttribute(moe_gemm2, cudaFuncAttributeMaxDynamicSharedMemorySize, SMEM2);

    build_groups<<<1, 256>>>(idx);

    dim3 g1(MTILES, NE, INTER / BN);   // (32, 8, 88)
    moe_gemm_fused<<<g1, NTHREADS, SMEM1>>>(x, w1, w3);

    dim3 g2(MTILES, NE, HID / BN);     // (32, 8, 32)
    moe_gemm2<<<g2, NTHREADS, SMEM2>>>(w2, ew);

    combine_kernel<<<(TOK * HID / 4 + 255) / 256, 256>>>(out);
}